// round 2
// baseline (speedup 1.0000x reference)
#include <cuda_runtime.h>
#include <math.h>

#define NL 24
#define D 1024
#define NH 16
#define SS 4096
#define HDIM 64
#define NHEAD_OUT 47   // 32 + 7 + 8

// -------- device scratch (allocation-free) --------
__device__ __align__(16) float g_q[D];
__device__ __align__(16) float g_x[D];        // layer input x (post prev LN2)
__device__ __align__(16) float g_xmid[D];     // LN1(x + attn_out)
__device__ __align__(16) float g_attnout[D];
__device__ __align__(16) float g_vals[D];
__device__ __align__(16) float g_h1[D];
__device__ __align__(16) float g_ffout[D];
__device__ __align__(16) float g_scores[NH * SS];

// -------- reductions (blockDim = 256) --------
__device__ __forceinline__ float warpReduceSum(float v) {
#pragma unroll
    for (int o = 16; o > 0; o >>= 1) v += __shfl_down_sync(0xffffffffu, v, o);
    return v;
}
__device__ __forceinline__ float warpReduceMax(float v) {
#pragma unroll
    for (int o = 16; o > 0; o >>= 1) v = fmaxf(v, __shfl_down_sync(0xffffffffu, v, o));
    return v;
}
__device__ __forceinline__ float blockReduceSum(float v, float* red) {
    int tid = threadIdx.x;
    v = warpReduceSum(v);
    if ((tid & 31) == 0) red[tid >> 5] = v;
    __syncthreads();
    if (tid < 32) {
        float t = (tid < 8) ? red[tid] : 0.f;
        t = warpReduceSum(t);
        if (tid == 0) red[0] = t;
    }
    __syncthreads();
    float r = red[0];
    __syncthreads();
    return r;
}
__device__ __forceinline__ float blockReduceMax(float v, float* red) {
    int tid = threadIdx.x;
    v = warpReduceMax(v);
    if ((tid & 31) == 0) red[tid >> 5] = v;
    __syncthreads();
    if (tid < 32) {
        float t = (tid < 8) ? red[tid] : -INFINITY;
        t = warpReduceMax(t);
        if (tid == 0) red[0] = t;
    }
    __syncthreads();
    float r = red[0];
    __syncthreads();
    return r;
}

// y = LN(a + b) * sc + bi  into shared xs[D]. 256 threads, float4 path.
__device__ __forceinline__ void load_ln(const float* __restrict__ a, const float* __restrict__ b,
                                        const float* __restrict__ sc, const float* __restrict__ bi,
                                        float* xs, float* red) {
    int tid = threadIdx.x;
    float4 av = ((const float4*)a)[tid];
    float4 bv = ((const float4*)b)[tid];
    av.x += bv.x; av.y += bv.y; av.z += bv.z; av.w += bv.w;
    float s1 = av.x + av.y + av.z + av.w;
    float s2 = av.x * av.x + av.y * av.y + av.z * av.z + av.w * av.w;
    float sum = blockReduceSum(s1, red);
    float sq  = blockReduceSum(s2, red);
    float mean = sum * (1.f / D);
    float inv = rsqrtf(sq * (1.f / D) - mean * mean + 1e-6f);
    float4 s4 = ((const float4*)sc)[tid];
    float4 b4 = ((const float4*)bi)[tid];
    float4 o;
    o.x = (av.x - mean) * inv * s4.x + b4.x;
    o.y = (av.y - mean) * inv * s4.y + b4.y;
    o.z = (av.z - mean) * inv * s4.z + b4.z;
    o.w = (av.w - mean) * inv * s4.w + b4.w;
    ((float4*)xs)[tid] = o;
}

// -------- kernel A: (optional LN2 of prev layer) + q/k/v GEMVs --------
// grid = 48 blocks (16 per matrix), 256 threads. Each block: 64 outputs, split-4 over K.
__global__ void __launch_bounds__(256) qkv_kernel(
    const float* __restrict__ xin, int first,
    const float* __restrict__ ln2s, const float* __restrict__ ln2b,
    const float* __restrict__ Wq, const float* __restrict__ Wk, const float* __restrict__ Wv,
    const float* __restrict__ bq, const float* __restrict__ bk, const float* __restrict__ bv,
    float* __restrict__ newc, int l) {
    __shared__ float xs[D];
    __shared__ float red[32];
    __shared__ float pr[4][64];
    int tid = threadIdx.x;
    if (first) {
        ((float4*)xs)[tid] = ((const float4*)xin)[tid];
    } else {
        load_ln(g_xmid, g_ffout, ln2s, ln2b, xs, red);
    }
    __syncthreads();
    if (blockIdx.x == 0) ((float4*)g_x)[tid] = ((float4*)xs)[tid];

    int m  = blockIdx.x >> 4;                       // 0=q, 1=k, 2=v
    int jg = ((blockIdx.x & 15) << 6) | (tid & 63); // output col
    int qq = tid >> 6;                              // K-quarter
    const float* W = (m == 0) ? Wq : ((m == 1) ? Wk : Wv);
    const float* B = (m == 0) ? bq : ((m == 1) ? bk : bv);
    const float* Wp = W + (size_t)(qq << 8) * D + jg;
    float acc = 0.f;
#pragma unroll 8
    for (int i = 0; i < 256; ++i) { acc += xs[(qq << 8) + i] * (*Wp); Wp += D; }
    pr[qq][tid & 63] = acc;
    __syncthreads();
    if (qq == 0) {
        float o = pr[0][tid] + pr[1][tid] + pr[2][tid] + pr[3][tid] + B[jg];
        if (m == 0) g_q[jg] = o;
        else {
            int plane = (m == 1) ? 1 : 0;  // plane0 = v, plane1 = k
            newc[((size_t)(l * 2 + plane) * SS + (SS - 1)) * D + jg] = o;
        }
    }
}

// -------- kernel B: fused cache shift + mask + attention scores --------
// grid = 4096 (one block per seq pos), 256 threads. Scalar gmem accesses:
// d_out cache region is offset 1071 floats -> not 16B aligned.
__global__ void __launch_bounds__(256) scores_kernel(
    const float* __restrict__ oldc, float* __restrict__ newc, int l) {
    int s = blockIdx.x;
    int tid = threadIdx.x;
    size_t vrow_new = ((size_t)(l * 2 + 0) * SS + s) * D;
    size_t krow_new = ((size_t)(l * 2 + 1) * SS + s) * D;
    bool copy = (s < SS - 1);
    const float* vsrc;
    const float* ksrc;
    if (copy) {
        vsrc = oldc + ((size_t)(l * 2 + 0) * SS + s + 1) * D;
        ksrc = oldc + ((size_t)(l * 2 + 1) * SS + s + 1) * D;
    } else {
        vsrc = newc + vrow_new;   // row written by qkv_kernel
        ksrc = newc + krow_new;
    }
    int e = tid << 2;
    float v0 = vsrc[e], v1 = vsrc[e + 1], v2 = vsrc[e + 2], v3 = vsrc[e + 3];
    float k0 = ksrc[e], k1 = ksrc[e + 1], k2 = ksrc[e + 2], k3 = ksrc[e + 3];
    if (copy) {
        float* vd = newc + vrow_new;
        float* kd = newc + krow_new;
        vd[e] = v0; vd[e + 1] = v1; vd[e + 2] = v2; vd[e + 3] = v3;
        kd[e] = k0; kd[e + 1] = k1; kd[e + 2] = k2; kd[e + 3] = k3;
    }
    int nz = (v0 != 0.f) || (v1 != 0.f) || (v2 != 0.f) || (v3 != 0.f);
    int any = __syncthreads_or(nz);
    float4 q4 = ((const float4*)g_q)[tid];
    float p = q4.x * k0 + q4.y * k1 + q4.z * k2 + q4.w * k3;
    // 16-thread (one head = 64 dims) subwarp reduction
    p += __shfl_down_sync(0xffffffffu, p, 8, 16);
    p += __shfl_down_sync(0xffffffffu, p, 4, 16);
    p += __shfl_down_sync(0xffffffffu, p, 2, 16);
    p += __shfl_down_sync(0xffffffffu, p, 1, 16);
    if ((tid & 15) == 0)
        g_scores[(tid >> 4) * SS + s] = any ? p * 0.125f : -INFINITY;  // 1/sqrt(64)
}

// -------- kernel C: per-head softmax + A·V --------
// grid = 16 (one block per head), 256 threads, probs in smem.
__global__ void __launch_bounds__(256) softmax_av_kernel(const float* __restrict__ newc, int l) {
    __shared__ float p[SS];
    __shared__ float red[32];
    __shared__ float racc[4][64];
    int h = blockIdx.x, tid = threadIdx.x;
    float mx = -INFINITY;
    for (int s = tid; s < SS; s += 256) {
        float v = g_scores[h * SS + s];
        p[s] = v;
        mx = fmaxf(mx, v);
    }
    mx = blockReduceMax(mx, red);
    float sum = 0.f;
    for (int s = tid; s < SS; s += 256) {
        float e = __expf(p[s] - mx);  // exp(-inf)=0 handles the mask
        p[s] = e;
        sum += e;
    }
    sum = blockReduceSum(sum, red);
    float inv = 1.f / sum;
    int d = tid & 63, sg = tid >> 6;
    const float* vp = newc + (size_t)(l * 2 + 0) * SS * D + h * HDIM + d;
    float acc = 0.f;
#pragma unroll 4
    for (int s = sg; s < SS; s += 4) acc += p[s] * vp[(size_t)s * D];
    racc[sg][d] = acc;
    __syncthreads();
    if (sg == 0)
        g_vals[h * HDIM + d] = (racc[0][d] + racc[1][d] + racc[2][d] + racc[3][d]) * inv;
}

// -------- kernels D/E/F: GEMV with mode-selected in/out and optional LN prologue --------
// mode 0: g_vals @ Wo + bo -> g_attnout
// mode 1: xmid = LN1(g_x + g_attnout); relu(xmid @ Wf1 + bf1) -> g_h1; block0 stores g_xmid
// mode 2: g_h1 @ Wf2 + bf2 -> g_ffout
// grid = 16 blocks, 256 threads.
__global__ void __launch_bounds__(256) gemv_kernel(
    int mode, const float* __restrict__ W, const float* __restrict__ B,
    const float* __restrict__ ln_s, const float* __restrict__ ln_b) {
    __shared__ float xs[D];
    __shared__ float red[32];
    __shared__ float pr[4][64];
    int tid = threadIdx.x;
    if (mode == 0) {
        ((float4*)xs)[tid] = ((const float4*)g_vals)[tid];
    } else if (mode == 1) {
        load_ln(g_x, g_attnout, ln_s, ln_b, xs, red);
    } else {
        ((float4*)xs)[tid] = ((const float4*)g_h1)[tid];
    }
    __syncthreads();
    if (mode == 1 && blockIdx.x == 0) ((float4*)g_xmid)[tid] = ((float4*)xs)[tid];

    int jg = (blockIdx.x << 6) | (tid & 63);
    int qq = tid >> 6;
    const float* Wp = W + (size_t)(qq << 8) * D + jg;
    float acc = 0.f;
#pragma unroll 8
    for (int i = 0; i < 256; ++i) { acc += xs[(qq << 8) + i] * (*Wp); Wp += D; }
    pr[qq][tid & 63] = acc;
    __syncthreads();
    if (qq == 0) {
        float o = pr[0][tid] + pr[1][tid] + pr[2][tid] + pr[3][tid] + B[jg];
        if (mode == 0)      g_attnout[jg] = o;
        else if (mode == 1) g_h1[jg] = fmaxf(o, 0.f);
        else                g_ffout[jg] = o;
    }
}

// -------- final: LN2(last layer) -> x out, then 3 head GEMVs (47 outputs) --------
__global__ void __launch_bounds__(256) final_kernel(
    const float* __restrict__ ln2s, const float* __restrict__ ln2b,
    const float* __restrict__ Wpi, const float* __restrict__ bpi,
    const float* __restrict__ Wvh, const float* __restrict__ bvh,
    const float* __restrict__ Wc,  const float* __restrict__ bc,
    float* __restrict__ out) {
    __shared__ float xs[D];
    __shared__ float red[32];
    int tid = threadIdx.x;
    load_ln(g_xmid, g_ffout, ln2s, ln2b, xs, red);
    __syncthreads();
    ((float4*)out)[tid] = ((float4*)xs)[tid];
    int w = tid >> 5, lane = tid & 31;
    for (int j = w; j < NHEAD_OUT; j += 8) {
        const float* W; const float* BB; int col, N;
        if (j < 32)      { W = Wpi; BB = bpi; col = j;      N = 32; }
        else if (j < 39) { W = Wvh; BB = bvh; col = j - 32; N = 7;  }
        else             { W = Wc;  BB = bc;  col = j - 39; N = 8;  }
        float a = 0.f;
        for (int i = lane; i < D; i += 32) a += xs[i] * W[(size_t)i * N + col];
        a = warpReduceSum(a);
        if (lane == 0) out[D + j] = a + BB[col];
    }
}

extern "C" void kernel_launch(void* const* d_in, const int* in_sizes, int n_in,
                              void* d_out, int out_size) {
    const float* x    = (const float*)d_in[0];
    const float* cach = (const float*)d_in[1];
    const float* Wv   = (const float*)d_in[2];
    const float* bv   = (const float*)d_in[3];
    const float* Wq   = (const float*)d_in[4];
    const float* bq   = (const float*)d_in[5];
    const float* Wk   = (const float*)d_in[6];
    const float* bk   = (const float*)d_in[7];
    const float* Wo   = (const float*)d_in[8];
    const float* bo   = (const float*)d_in[9];
    const float* ln1s = (const float*)d_in[10];
    const float* ln1b = (const float*)d_in[11];
    const float* ln2s = (const float*)d_in[12];
    const float* ln2b = (const float*)d_in[13];
    const float* Wf1  = (const float*)d_in[14];
    const float* bf1  = (const float*)d_in[15];
    const float* Wf2  = (const float*)d_in[16];
    const float* bf2  = (const float*)d_in[17];
    const float* Wpi  = (const float*)d_in[18];
    const float* bpi  = (const float*)d_in[19];
    const float* Wvh  = (const float*)d_in[20];
    const float* bvh  = (const float*)d_in[21];
    const float* Wc   = (const float*)d_in[22];
    const float* bc   = (const float*)d_in[23];

    float* out  = (float*)d_out;
    float* newc = out + (D + NHEAD_OUT);  // cache region of flattened output tuple

    for (int l = 0; l < NL; ++l) {
        size_t mo = (size_t)l * D * D;
        size_t vo = (size_t)l * D;
        const float* p2s = (l > 0) ? (ln2s + (size_t)(l - 1) * D) : ln2s;
        const float* p2b = (l > 0) ? (ln2b + (size_t)(l - 1) * D) : ln2b;

        qkv_kernel<<<48, 256>>>(x, (l == 0) ? 1 : 0, p2s, p2b,
                                Wq + mo, Wk + mo, Wv + mo,
                                bq + vo, bk + vo, bv + vo, newc, l);
        scores_kernel<<<SS, 256>>>(cach, newc, l);
        softmax_av_kernel<<<NH, 256>>>(newc, l);
        gemv_kernel<<<16, 256>>>(0, Wo + mo, bo + vo, ln1s + vo, ln1b + vo);
        gemv_kernel<<<16, 256>>>(1, Wf1 + mo, bf1 + vo, ln1s + vo, ln1b + vo);
        gemv_kernel<<<16, 256>>>(2, Wf2 + mo, bf2 + vo, ln1s + vo, ln1b + vo);
    }
    final_kernel<<<1, 256>>>(ln2s + (size_t)(NL - 1) * D, ln2b + (size_t)(NL - 1) * D,
                             Wpi, bpi, Wvh, bvh, Wc, bc, out);
}

// round 3
// speedup vs baseline: 4.2629x; 4.2629x over previous
#include <cuda_runtime.h>
#include <math.h>

#define NL 24
#define D 1024
#define NH 16
#define SS 4096
#define HDIM 64
#define NHEAD_OUT 47   // 32 + 7 + 8

// -------- device scratch (allocation-free) --------
__device__ __align__(16) float g_q[D];
__device__ __align__(16) float g_x[D];        // layer input x (post prev LN2)
__device__ __align__(16) float g_xmid[D];     // LN1(x + attn_out)
__device__ __align__(16) float g_attnout[D];
__device__ __align__(16) float g_h1[D];
__device__ __align__(16) float g_ffout[D];
__device__ __align__(16) float g_scores[NH * SS];
__device__ __align__(16) float g_av_part[16 * D];  // [chunk][h*64+d]
__device__ float g_smax[NH];
__device__ float g_sinv[NH];

// -------- reductions (blockDim = 256) --------
__device__ __forceinline__ float warpReduceSum(float v) {
#pragma unroll
    for (int o = 16; o > 0; o >>= 1) v += __shfl_down_sync(0xffffffffu, v, o);
    return v;
}
__device__ __forceinline__ float warpReduceMax(float v) {
#pragma unroll
    for (int o = 16; o > 0; o >>= 1) v = fmaxf(v, __shfl_down_sync(0xffffffffu, v, o));
    return v;
}
__device__ __forceinline__ float blockReduceSum(float v, float* red) {
    int tid = threadIdx.x;
    v = warpReduceSum(v);
    if ((tid & 31) == 0) red[tid >> 5] = v;
    __syncthreads();
    if (tid < 32) {
        float t = (tid < 8) ? red[tid] : 0.f;
        t = warpReduceSum(t);
        if (tid == 0) red[0] = t;
    }
    __syncthreads();
    float r = red[0];
    __syncthreads();
    return r;
}
__device__ __forceinline__ float blockReduceMax(float v, float* red) {
    int tid = threadIdx.x;
    v = warpReduceMax(v);
    if ((tid & 31) == 0) red[tid >> 5] = v;
    __syncthreads();
    if (tid < 32) {
        float t = (tid < 8) ? red[tid] : -INFINITY;
        t = warpReduceMax(t);
        if (tid == 0) red[0] = t;
    }
    __syncthreads();
    float r = red[0];
    __syncthreads();
    return r;
}

// y = LN(a + b) * sc + bi  into shared xs[D]. 256 threads, float4 path.
__device__ __forceinline__ void load_ln(const float* __restrict__ a, const float* __restrict__ b,
                                        const float* __restrict__ sc, const float* __restrict__ bi,
                                        float* xs, float* red) {
    int tid = threadIdx.x;
    float4 av = ((const float4*)a)[tid];
    float4 bv = ((const float4*)b)[tid];
    av.x += bv.x; av.y += bv.y; av.z += bv.z; av.w += bv.w;
    float s1 = av.x + av.y + av.z + av.w;
    float s2 = av.x * av.x + av.y * av.y + av.z * av.z + av.w * av.w;
    float sum = blockReduceSum(s1, red);
    float sq  = blockReduceSum(s2, red);
    float mean = sum * (1.f / D);
    float inv = rsqrtf(sq * (1.f / D) - mean * mean + 1e-6f);
    float4 s4 = ((const float4*)sc)[tid];
    float4 b4 = ((const float4*)bi)[tid];
    float4 o;
    o.x = (av.x - mean) * inv * s4.x + b4.x;
    o.y = (av.y - mean) * inv * s4.y + b4.y;
    o.z = (av.z - mean) * inv * s4.z + b4.z;
    o.w = (av.w - mean) * inv * s4.w + b4.w;
    ((float4*)xs)[tid] = o;
}

// Shared GEMV core: 8 outputs per block, 32-way K-split, 256 threads.
// xs[D] in shared; returns the output value for j = jbase + w to the caller
// via a lambda-free mode switch in each kernel.
// Layout: jo = tid&7 (output within block), ks = tid>>3 (K-slice, 32 elems).
__device__ __forceinline__ float gemv8_core(const float* __restrict__ W, const float* xs,
                                            int jbase, float pr[8][33]) {
    int tid = threadIdx.x;
    int jo = tid & 7;
    int ks = tid >> 3;                 // 0..31
    const float* Wp = W + (size_t)(ks << 5) * D + jbase + jo;
    float acc = 0.f;
#pragma unroll
    for (int i = 0; i < 32; ++i) { acc += xs[(ks << 5) + i] * (*Wp); Wp += D; }
    pr[jo][ks] = acc;
    __syncthreads();
    // warp w reduces output w
    int w = tid >> 5, lane = tid & 31;
    float v = pr[w][lane];
    v = warpReduceSum(v);
    return v;   // valid on lane 0 of each warp
}

// -------- kernel A: (optional LN2 of prev layer) + q/k/v GEMVs --------
// grid = 384 (128 per matrix), 256 threads.
__global__ void __launch_bounds__(256) qkv_kernel(
    const float* __restrict__ xin, int first,
    const float* __restrict__ ln2s, const float* __restrict__ ln2b,
    const float* __restrict__ Wq, const float* __restrict__ Wk, const float* __restrict__ Wv,
    const float* __restrict__ bq, const float* __restrict__ bk, const float* __restrict__ bv,
    float* __restrict__ newc, int l) {
    __shared__ float xs[D];
    __shared__ float red[32];
    __shared__ float pr[8][33];
    int tid = threadIdx.x;
    if (first) {
        ((float4*)xs)[tid] = ((const float4*)xin)[tid];
    } else {
        load_ln(g_xmid, g_ffout, ln2s, ln2b, xs, red);
    }
    __syncthreads();
    if (blockIdx.x == 0) ((float4*)g_x)[tid] = ((float4*)xs)[tid];

    int m  = blockIdx.x >> 7;                 // 0=q, 1=k, 2=v
    int jbase = (blockIdx.x & 127) << 3;
    const float* W = (m == 0) ? Wq : ((m == 1) ? Wk : Wv);
    const float* B = (m == 0) ? bq : ((m == 1) ? bk : bv);
    float v = gemv8_core(W, xs, jbase, pr);
    int w = tid >> 5, lane = tid & 31;
    if (lane == 0) {
        int j = jbase + w;
        float o = v + B[j];
        if (m == 0) g_q[j] = o;
        else {
            int plane = (m == 1) ? 1 : 0;     // plane0 = v, plane1 = k
            newc[((size_t)(l * 2 + plane) * SS + (SS - 1)) * D + j] = o;
        }
    }
}

// -------- kernel B: fused cache shift + mask + attention scores --------
// grid = 4096 (one block per seq pos), 256 threads.
__global__ void __launch_bounds__(256) scores_kernel(
    const float* __restrict__ oldc, float* __restrict__ newc, int l) {
    int s = blockIdx.x;
    int tid = threadIdx.x;
    size_t vrow_new = ((size_t)(l * 2 + 0) * SS + s) * D;
    size_t krow_new = ((size_t)(l * 2 + 1) * SS + s) * D;
    bool copy = (s < SS - 1);
    const float* vsrc;
    const float* ksrc;
    if (copy) {
        vsrc = oldc + ((size_t)(l * 2 + 0) * SS + s + 1) * D;
        ksrc = oldc + ((size_t)(l * 2 + 1) * SS + s + 1) * D;
    } else {
        vsrc = newc + vrow_new;   // row written by qkv_kernel
        ksrc = newc + krow_new;
    }
    int e = tid << 2;
    float v0 = vsrc[e], v1 = vsrc[e + 1], v2 = vsrc[e + 2], v3 = vsrc[e + 3];
    float k0 = ksrc[e], k1 = ksrc[e + 1], k2 = ksrc[e + 2], k3 = ksrc[e + 3];
    if (copy) {
        float* vd = newc + vrow_new;
        float* kd = newc + krow_new;
        vd[e] = v0; vd[e + 1] = v1; vd[e + 2] = v2; vd[e + 3] = v3;
        kd[e] = k0; kd[e + 1] = k1; kd[e + 2] = k2; kd[e + 3] = k3;
    }
    int nz = (v0 != 0.f) || (v1 != 0.f) || (v2 != 0.f) || (v3 != 0.f);
    int any = __syncthreads_or(nz);
    float4 q4 = ((const float4*)g_q)[tid];
    float p = q4.x * k0 + q4.y * k1 + q4.z * k2 + q4.w * k3;
    // 16-thread (one head = 64 dims) subwarp reduction
    p += __shfl_down_sync(0xffffffffu, p, 8, 16);
    p += __shfl_down_sync(0xffffffffu, p, 4, 16);
    p += __shfl_down_sync(0xffffffffu, p, 2, 16);
    p += __shfl_down_sync(0xffffffffu, p, 1, 16);
    if ((tid & 15) == 0)
        g_scores[(tid >> 4) * SS + s] = any ? p * 0.125f : -INFINITY;  // 1/sqrt(64)
}

// -------- kernel C1: per-head softmax stats --------
// grid = 16, 256 threads.
__global__ void __launch_bounds__(256) stats_kernel() {
    __shared__ float red[32];
    int h = blockIdx.x, tid = threadIdx.x;
    float mx = -INFINITY;
    float loc[16];
#pragma unroll
    for (int i = 0; i < 16; ++i) {
        float v = g_scores[h * SS + (i << 8) + tid];
        loc[i] = v;
        mx = fmaxf(mx, v);
    }
    mx = blockReduceMax(mx, red);
    float sum = 0.f;
#pragma unroll
    for (int i = 0; i < 16; ++i) sum += __expf(loc[i] - mx);
    sum = blockReduceSum(sum, red);
    if (tid == 0) { g_smax[h] = mx; g_sinv[h] = 1.f / sum; }
}

// -------- kernel C2: partial A·V --------
// grid = 256 (h = b>>4, chunk = b&15), 256 threads. Each block: 256 s-positions, 64 dims.
__global__ void __launch_bounds__(256) av_kernel(const float* __restrict__ newc, int l) {
    __shared__ float p[256];
    __shared__ float racc[4][64];
    int h = blockIdx.x >> 4, c = blockIdx.x & 15;
    int tid = threadIdx.x;
    int s0 = c << 8;
    float mx = g_smax[h], inv = g_sinv[h];
    p[tid] = __expf(g_scores[h * SS + s0 + tid] - mx) * inv;
    __syncthreads();
    int d = tid & 63, sq = tid >> 6;
    const float* vp = newc + (size_t)(l * 2 + 0) * SS * D
                      + (size_t)(s0 + (sq << 6)) * D + h * HDIM + d;
    float acc = 0.f;
#pragma unroll 8
    for (int i = 0; i < 64; ++i) acc += p[(sq << 6) + i] * vp[(size_t)i * D];
    racc[sq][d] = acc;
    __syncthreads();
    if (sq == 0)
        g_av_part[c * D + h * HDIM + d] = racc[0][d] + racc[1][d] + racc[2][d] + racc[3][d];
}

// -------- kernels D/E/F: GEMV, grid = 128 blocks --------
// mode 0: (reduce g_av_part) @ Wo + bo -> g_attnout
// mode 1: xmid = LN1(g_x + g_attnout); relu(xmid @ Wf1 + bf1) -> g_h1; block0 stores g_xmid
// mode 2: g_h1 @ Wf2 + bf2 -> g_ffout
__global__ void __launch_bounds__(256) gemv_kernel(
    int mode, const float* __restrict__ W, const float* __restrict__ B,
    const float* __restrict__ ln_s, const float* __restrict__ ln_b) {
    __shared__ float xs[D];
    __shared__ float red[32];
    __shared__ float pr[8][33];
    int tid = threadIdx.x;
    if (mode == 0) {
        float4 a = ((const float4*)g_av_part)[tid];
#pragma unroll
        for (int c = 1; c < 16; ++c) {
            float4 b = ((const float4*)g_av_part)[c * 256 + tid];
            a.x += b.x; a.y += b.y; a.z += b.z; a.w += b.w;
        }
        ((float4*)xs)[tid] = a;
    } else if (mode == 1) {
        load_ln(g_x, g_attnout, ln_s, ln_b, xs, red);
    } else {
        ((float4*)xs)[tid] = ((const float4*)g_h1)[tid];
    }
    __syncthreads();
    if (mode == 1 && blockIdx.x == 0) ((float4*)g_xmid)[tid] = ((float4*)xs)[tid];

    int jbase = blockIdx.x << 3;
    float v = gemv8_core(W, xs, jbase, pr);
    int w = tid >> 5, lane = tid & 31;
    if (lane == 0) {
        int j = jbase + w;
        float o = v + B[j];
        if (mode == 0)      g_attnout[j] = o;
        else if (mode == 1) g_h1[j] = fmaxf(o, 0.f);
        else                g_ffout[j] = o;
    }
}

// -------- final: LN2(last layer) -> x out, then 3 head GEMVs (47 outputs) --------
__global__ void __launch_bounds__(256) final_kernel(
    const float* __restrict__ ln2s, const float* __restrict__ ln2b,
    const float* __restrict__ Wpi, const float* __restrict__ bpi,
    const float* __restrict__ Wvh, const float* __restrict__ bvh,
    const float* __restrict__ Wc,  const float* __restrict__ bc,
    float* __restrict__ out) {
    __shared__ float xs[D];
    __shared__ float red[32];
    int tid = threadIdx.x;
    load_ln(g_xmid, g_ffout, ln2s, ln2b, xs, red);
    __syncthreads();
    ((float4*)out)[tid] = ((float4*)xs)[tid];
    int w = tid >> 5, lane = tid & 31;
    for (int j = w; j < NHEAD_OUT; j += 8) {
        const float* W; const float* BB; int col, N;
        if (j < 32)      { W = Wpi; BB = bpi; col = j;      N = 32; }
        else if (j < 39) { W = Wvh; BB = bvh; col = j - 32; N = 7;  }
        else             { W = Wc;  BB = bc;  col = j - 39; N = 8;  }
        float a = 0.f;
        for (int i = lane; i < D; i += 32) a += xs[i] * W[(size_t)i * N + col];
        a = warpReduceSum(a);
        if (lane == 0) out[D + j] = a + BB[col];
    }
}

extern "C" void kernel_launch(void* const* d_in, const int* in_sizes, int n_in,
                              void* d_out, int out_size) {
    const float* x    = (const float*)d_in[0];
    const float* cach = (const float*)d_in[1];
    const float* Wv   = (const float*)d_in[2];
    const float* bv   = (const float*)d_in[3];
    const float* Wq   = (const float*)d_in[4];
    const float* bq   = (const float*)d_in[5];
    const float* Wk   = (const float*)d_in[6];
    const float* bk   = (const float*)d_in[7];
    const float* Wo   = (const float*)d_in[8];
    const float* bo   = (const float*)d_in[9];
    const float* ln1s = (const float*)d_in[10];
    const float* ln1b = (const float*)d_in[11];
    const float* ln2s = (const float*)d_in[12];
    const float* ln2b = (const float*)d_in[13];
    const float* Wf1  = (const float*)d_in[14];
    const float* bf1  = (const float*)d_in[15];
    const float* Wf2  = (const float*)d_in[16];
    const float* bf2  = (const float*)d_in[17];
    const float* Wpi  = (const float*)d_in[18];
    const float* bpi  = (const float*)d_in[19];
    const float* Wvh  = (const float*)d_in[20];
    const float* bvh  = (const float*)d_in[21];
    const float* Wc   = (const float*)d_in[22];
    const float* bc   = (const float*)d_in[23];

    float* out  = (float*)d_out;
    float* newc = out + (D + NHEAD_OUT);  // cache region of flattened output tuple

    for (int l = 0; l < NL; ++l) {
        size_t mo = (size_t)l * D * D;
        size_t vo = (size_t)l * D;
        const float* p2s = (l > 0) ? (ln2s + (size_t)(l - 1) * D) : ln2s;
        const float* p2b = (l > 0) ? (ln2b + (size_t)(l - 1) * D) : ln2b;

        qkv_kernel<<<384, 256>>>(x, (l == 0) ? 1 : 0, p2s, p2b,
                                 Wq + mo, Wk + mo, Wv + mo,
                                 bq + vo, bk + vo, bv + vo, newc, l);
        scores_kernel<<<SS, 256>>>(cach, newc, l);
        stats_kernel<<<NH, 256>>>();
        av_kernel<<<256, 256>>>(newc, l);
        gemv_kernel<<<128, 256>>>(0, Wo + mo, bo + vo, ln1s + vo, ln1b + vo);
        gemv_kernel<<<128, 256>>>(1, Wf1 + mo, bf1 + vo, ln1s + vo, ln1b + vo);
        gemv_kernel<<<128, 256>>>(2, Wf2 + mo, bf2 + vo, ln1s + vo, ln1b + vo);
    }
    final_kernel<<<1, 256>>>(ln2s + (size_t)(NL - 1) * D, ln2b + (size_t)(NL - 1) * D,
                             Wpi, bpi, Wvh, bvh, Wc, bc, out);
}